// round 1
// baseline (speedup 1.0000x reference)
#include <cuda_runtime.h>
#include <cstdint>
#include <cstddef>

// ============================================================================
// SwinMSA: x[1024,64,512] -> qkv -> windowed attention (+rel bias +mask) -> proj
// Round 1: correct fp32 SIMT baseline.
//   k1: qkv GEMM [65536,512]x[512,1536], epilogue scatters to Q/K/V [b][h][n][d]
//       (adds qkv_b, pre-scales Q by 1/sqrt(32))
//   k2: per-(window,head) fused attention block (16384 blocks)
//   k3: proj GEMM [65536,512]x[512,512] + proj_b -> d_out
// ============================================================================

namespace {
constexpr int HEADS = 16;
constexpr int HD    = 32;
constexpr int NT    = 64;     // tokens per window
constexpr int BW    = 1024;   // windows (batch*nw)
constexpr int CIN   = 512;
constexpr int CQKV  = 1536;
constexpr float ATT_SCALE = 0.17677669529663688f;  // 32^-0.5
}

// Scratch (allocation-free rule: __device__ globals)
__device__ float g_Q[(size_t)BW * HEADS * NT * HD];   // 134 MB
__device__ float g_K[(size_t)BW * HEADS * NT * HD];
__device__ float g_V[(size_t)BW * HEADS * NT * HD];
__device__ float g_O[(size_t)BW * NT * CIN];          // [b][n][h*32+d]

// ----------------------------------------------------------------------------
// Kernel 1: QKV GEMM.  C = X @ W + b, scattered into g_Q/g_K/g_V.
// Tiles: 128x128x16, 256 threads, 8x8 per thread.
// ----------------------------------------------------------------------------
__global__ __launch_bounds__(256, 2)
void qkv_gemm_kernel(const float* __restrict__ X,
                     const float* __restrict__ W,
                     const float* __restrict__ bias)
{
    __shared__ float As[16][132];   // transposed A tile (pad vs bank conflicts)
    __shared__ float Bs[16][128];

    const int tid = threadIdx.x;
    const int tx  = tid & 15;
    const int ty  = tid >> 4;
    const int M0  = blockIdx.x * 128;
    const int N0  = blockIdx.y * 128;

    const int arow = tid >> 2;          // 0..63
    const int ak   = (tid & 3) << 2;    // 0,4,8,12
    const int brow = tid >> 5;          // 0..7
    const int bcol = (tid & 31) << 2;   // 0..124

    float acc[8][8] = {};

    for (int kt = 0; kt < CIN; kt += 16) {
        float4 a0 = *(const float4*)&X[(size_t)(M0 + arow)      * CIN + kt + ak];
        float4 a1 = *(const float4*)&X[(size_t)(M0 + arow + 64) * CIN + kt + ak];
        float4 b0 = *(const float4*)&W[(size_t)(kt + brow)     * CQKV + N0 + bcol];
        float4 b1 = *(const float4*)&W[(size_t)(kt + brow + 8) * CQKV + N0 + bcol];
        __syncthreads();
        As[ak + 0][arow] = a0.x; As[ak + 1][arow] = a0.y;
        As[ak + 2][arow] = a0.z; As[ak + 3][arow] = a0.w;
        As[ak + 0][arow + 64] = a1.x; As[ak + 1][arow + 64] = a1.y;
        As[ak + 2][arow + 64] = a1.z; As[ak + 3][arow + 64] = a1.w;
        *(float4*)&Bs[brow][bcol]     = b0;
        *(float4*)&Bs[brow + 8][bcol] = b1;
        __syncthreads();

        #pragma unroll
        for (int k = 0; k < 16; ++k) {
            float a[8], b[8];
            *(float4*)&a[0] = *(const float4*)&As[k][ty * 4];
            *(float4*)&a[4] = *(const float4*)&As[k][64 + ty * 4];
            *(float4*)&b[0] = *(const float4*)&Bs[k][tx * 4];
            *(float4*)&b[4] = *(const float4*)&Bs[k][64 + tx * 4];
            #pragma unroll
            for (int i = 0; i < 8; ++i)
                #pragma unroll
                for (int j = 0; j < 8; ++j)
                    acc[i][j] = fmaf(a[i], b[j], acc[i][j]);
        }
    }

    // Epilogue: add bias, scatter to Q/K/V [b][h][n][d]; Q pre-scaled.
    #pragma unroll
    for (int i = 0; i < 8; ++i) {
        const int r    = (i < 4) ? (ty * 4 + i) : (64 + ty * 4 + (i - 4));
        const int t    = M0 + r;
        const int bwin = t >> 6;
        const int n    = t & 63;
        #pragma unroll
        for (int jj = 0; jj < 2; ++jj) {
            const int c0  = N0 + jj * 64 + tx * 4;   // 4-aligned, never straddles 32/96 bins
            const int h   = c0 / 96;
            const int rem = c0 - h * 96;
            const int sel = rem >> 5;
            const int d   = rem & 31;
            float* dst = (sel == 0) ? g_Q : (sel == 1) ? g_K : g_V;
            const size_t off = ((size_t)(bwin * HEADS + h) * NT + n) * HD + d;
            const float m = (sel == 0) ? ATT_SCALE : 1.0f;
            float4 o;
            o.x = (acc[i][jj * 4 + 0] + bias[c0 + 0]) * m;
            o.y = (acc[i][jj * 4 + 1] + bias[c0 + 1]) * m;
            o.z = (acc[i][jj * 4 + 2] + bias[c0 + 2]) * m;
            o.w = (acc[i][jj * 4 + 3] + bias[c0 + 3]) * m;
            *(float4*)&dst[off] = o;
        }
    }
}

// ----------------------------------------------------------------------------
// Kernel 2: fused attention. One block per (window b, head h).
// S = Q Kt (Q pre-scaled) + bias_table[rel_index][h] + mask[b%256]; softmax; O = P V
// ----------------------------------------------------------------------------
__global__ __launch_bounds__(256)
void attn_kernel(const float* __restrict__ mask,
                 const float* __restrict__ bias_table,
                 const int*   __restrict__ rel_index)
{
    __shared__ float Qs[64][33];
    __shared__ float Kt[32][68];   // transposed K: Kt[d][j]
    __shared__ float Vs[64][32];
    __shared__ float Ss[64][65];

    const int bid = blockIdx.x;      // == b*16 + h == layout index of g_Q tiles
    const int b   = bid >> 4;
    const int h   = bid & 15;
    const int w   = b & 255;         // mask window index
    const int tid = threadIdx.x;

    const float* qp = g_Q + (size_t)bid * NT * HD;
    const float* kp = g_K + (size_t)bid * NT * HD;
    const float* vp = g_V + (size_t)bid * NT * HD;

    // ---- load tiles (8 floats per thread per tensor) ----
    {
        const int e   = tid << 3;
        const int row = e >> 5;
        const int col = e & 31;
        float4 q0 = *(const float4*)(qp + e);
        float4 q1 = *(const float4*)(qp + e + 4);
        Qs[row][col + 0] = q0.x; Qs[row][col + 1] = q0.y;
        Qs[row][col + 2] = q0.z; Qs[row][col + 3] = q0.w;
        Qs[row][col + 4] = q1.x; Qs[row][col + 5] = q1.y;
        Qs[row][col + 6] = q1.z; Qs[row][col + 7] = q1.w;
        float4 k0 = *(const float4*)(kp + e);
        float4 k1 = *(const float4*)(kp + e + 4);
        Kt[col + 0][row] = k0.x; Kt[col + 1][row] = k0.y;
        Kt[col + 2][row] = k0.z; Kt[col + 3][row] = k0.w;
        Kt[col + 4][row] = k1.x; Kt[col + 5][row] = k1.y;
        Kt[col + 6][row] = k1.z; Kt[col + 7][row] = k1.w;
        *(float4*)&Vs[row][col]     = *(const float4*)(vp + e);
        *(float4*)&Vs[row][col + 4] = *(const float4*)(vp + e + 4);
    }
    __syncthreads();

    // ---- S = Q Kt : thread does row i, 16 cols ----
    {
        const int i  = tid >> 2;
        const int jb = (tid & 3) << 4;
        float acc[16] = {};
        #pragma unroll
        for (int d = 0; d < 32; ++d) {
            const float qv = Qs[i][d];
            float kv[16];
            *(float4*)&kv[0]  = *(const float4*)&Kt[d][jb];
            *(float4*)&kv[4]  = *(const float4*)&Kt[d][jb + 4];
            *(float4*)&kv[8]  = *(const float4*)&Kt[d][jb + 8];
            *(float4*)&kv[12] = *(const float4*)&Kt[d][jb + 12];
            #pragma unroll
            for (int m = 0; m < 16; ++m) acc[m] = fmaf(qv, kv[m], acc[m]);
        }
        const float* mrow = mask + ((size_t)w * 64 + i) * 64;
        const int*   rrow = rel_index + i * 64;
        #pragma unroll
        for (int m = 0; m < 16; ++m) {
            const int j = jb + m;
            Ss[i][j] = acc[m] + bias_table[rrow[j] * HEADS + h] + mrow[j];
        }
    }
    __syncthreads();

    // ---- row softmax: each warp handles 8 rows ----
    {
        const int warp = tid >> 5, lane = tid & 31;
        for (int rr = 0; rr < 8; ++rr) {
            const int r = warp * 8 + rr;
            float s0 = Ss[r][lane], s1 = Ss[r][lane + 32];
            float mx = fmaxf(s0, s1);
            #pragma unroll
            for (int o = 16; o; o >>= 1) mx = fmaxf(mx, __shfl_xor_sync(0xffffffffu, mx, o));
            float e0 = __expf(s0 - mx), e1 = __expf(s1 - mx);
            float sum = e0 + e1;
            #pragma unroll
            for (int o = 16; o; o >>= 1) sum += __shfl_xor_sync(0xffffffffu, sum, o);
            const float inv = 1.0f / sum;
            Ss[r][lane]      = e0 * inv;
            Ss[r][lane + 32] = e1 * inv;
        }
    }
    __syncthreads();

    // ---- O = P V : thread does row oi, 8 d's ----
    {
        const int oi = tid >> 2;
        const int db = (tid & 3) << 3;
        float o[8] = {};
        #pragma unroll 8
        for (int j = 0; j < 64; ++j) {
            const float p = Ss[oi][j];
            float vv[8];
            *(float4*)&vv[0] = *(const float4*)&Vs[j][db];
            *(float4*)&vv[4] = *(const float4*)&Vs[j][db + 4];
            #pragma unroll
            for (int m = 0; m < 8; ++m) o[m] = fmaf(p, vv[m], o[m]);
        }
        const size_t off = ((size_t)(b * NT + oi)) * CIN + h * HD + db;
        *(float4*)&g_O[off]     = make_float4(o[0], o[1], o[2], o[3]);
        *(float4*)&g_O[off + 4] = make_float4(o[4], o[5], o[6], o[7]);
    }
}

// ----------------------------------------------------------------------------
// Kernel 3: proj GEMM.  out = g_O @ proj_w + proj_b.
// ----------------------------------------------------------------------------
__global__ __launch_bounds__(256, 2)
void proj_gemm_kernel(const float* __restrict__ W,
                      const float* __restrict__ bias,
                      float* __restrict__ out)
{
    __shared__ float As[16][132];
    __shared__ float Bs[16][128];

    const int tid = threadIdx.x;
    const int tx  = tid & 15;
    const int ty  = tid >> 4;
    const int M0  = blockIdx.x * 128;
    const int N0  = blockIdx.y * 128;

    const int arow = tid >> 2;
    const int ak   = (tid & 3) << 2;
    const int brow = tid >> 5;
    const int bcol = (tid & 31) << 2;

    float acc[8][8] = {};

    for (int kt = 0; kt < CIN; kt += 16) {
        float4 a0 = *(const float4*)&g_O[(size_t)(M0 + arow)      * CIN + kt + ak];
        float4 a1 = *(const float4*)&g_O[(size_t)(M0 + arow + 64) * CIN + kt + ak];
        float4 b0 = *(const float4*)&W[(size_t)(kt + brow)     * CIN + N0 + bcol];
        float4 b1 = *(const float4*)&W[(size_t)(kt + brow + 8) * CIN + N0 + bcol];
        __syncthreads();
        As[ak + 0][arow] = a0.x; As[ak + 1][arow] = a0.y;
        As[ak + 2][arow] = a0.z; As[ak + 3][arow] = a0.w;
        As[ak + 0][arow + 64] = a1.x; As[ak + 1][arow + 64] = a1.y;
        As[ak + 2][arow + 64] = a1.z; As[ak + 3][arow + 64] = a1.w;
        *(float4*)&Bs[brow][bcol]     = b0;
        *(float4*)&Bs[brow + 8][bcol] = b1;
        __syncthreads();

        #pragma unroll
        for (int k = 0; k < 16; ++k) {
            float a[8], b[8];
            *(float4*)&a[0] = *(const float4*)&As[k][ty * 4];
            *(float4*)&a[4] = *(const float4*)&As[k][64 + ty * 4];
            *(float4*)&b[0] = *(const float4*)&Bs[k][tx * 4];
            *(float4*)&b[4] = *(const float4*)&Bs[k][64 + tx * 4];
            #pragma unroll
            for (int i = 0; i < 8; ++i)
                #pragma unroll
                for (int j = 0; j < 8; ++j)
                    acc[i][j] = fmaf(a[i], b[j], acc[i][j]);
        }
    }

    #pragma unroll
    for (int i = 0; i < 8; ++i) {
        const int r = (i < 4) ? (ty * 4 + i) : (64 + ty * 4 + (i - 4));
        const size_t rowoff = (size_t)(M0 + r) * CIN;
        #pragma unroll
        for (int jj = 0; jj < 2; ++jj) {
            const int c0 = N0 + jj * 64 + tx * 4;
            float4 o;
            o.x = acc[i][jj * 4 + 0] + bias[c0 + 0];
            o.y = acc[i][jj * 4 + 1] + bias[c0 + 1];
            o.z = acc[i][jj * 4 + 2] + bias[c0 + 2];
            o.w = acc[i][jj * 4 + 3] + bias[c0 + 3];
            *(float4*)&out[rowoff + c0] = o;
        }
    }
}

// ----------------------------------------------------------------------------
extern "C" void kernel_launch(void* const* d_in, const int* in_sizes, int n_in,
                              void* d_out, int out_size)
{
    (void)in_sizes; (void)n_in; (void)out_size;
    const float* x          = (const float*)d_in[0];
    const float* mask       = (const float*)d_in[1];
    const float* qkv_w      = (const float*)d_in[2];
    const float* qkv_b      = (const float*)d_in[3];
    const float* proj_w     = (const float*)d_in[4];
    const float* proj_b     = (const float*)d_in[5];
    const float* bias_table = (const float*)d_in[6];
    const int*   rel_index  = (const int*)d_in[7];
    float* out = (float*)d_out;

    qkv_gemm_kernel<<<dim3(512, 12), 256>>>(x, qkv_w, qkv_b);
    attn_kernel<<<BW * HEADS, 256>>>(mask, bias_table, rel_index);
    proj_gemm_kernel<<<dim3(512, 4), 256>>>(proj_w, proj_b, out);
}

// round 5
// speedup vs baseline: 1.1734x; 1.1734x over previous
#include <cuda_runtime.h>
#include <cstdint>
#include <cstddef>

// ============================================================================
// SwinMSA round 5: mma.sync 3xTF32 (error-compensated) GEMMs.
//   Fix vs round 4 (rel_err 1.55e-3): split each fp32 operand into
//   tf32 hi + tf32 lo and accumulate Ahi*Bhi + Ahi*Blo + Alo*Bhi.
//   Per-product residual ~2^-22 -> output rel_err ~1e-5.
//   k0a/k0b: transpose qkv_w / proj_w into [N,K] K-major
//   k1: 3xtf32 GEMM 128x128 -> scatter Q/K/V (+qkv_b, Q*scale)
//   k2: fused per-(window,head) attention (proven round-1 fp32 SIMT)
//   k3: 3xtf32 GEMM -> out (+proj_b)
// ============================================================================

namespace {
constexpr int HEADS = 16;
constexpr int HD    = 32;
constexpr int NT    = 64;
constexpr int BW    = 1024;
constexpr int CIN   = 512;
constexpr int CQKV  = 1536;
constexpr float ATT_SCALE = 0.17677669529663688f;
constexpr int PITCH = 20;   // floats per smem row: conflict-free + 16B aligned
}

// Scratch (__device__ globals: allocation-free rule)
__device__ float g_Q[(size_t)BW * HEADS * NT * HD];
__device__ float g_K[(size_t)BW * HEADS * NT * HD];
__device__ float g_V[(size_t)BW * HEADS * NT * HD];
__device__ float g_O[(size_t)BW * NT * CIN];
__device__ float g_WqkvT[(size_t)CQKV * CIN];
__device__ float g_WprojT[(size_t)CIN * CIN];

__device__ __forceinline__ uint32_t smem_u32(const void* p) {
    uint32_t a;
    asm("{ .reg .u64 t; cvta.to.shared.u64 t, %1; cvt.u32.u64 %0, t; }"
        : "=r"(a) : "l"(p));
    return a;
}
__device__ __forceinline__ void cp_async16(uint32_t saddr, const void* gaddr) {
    asm volatile("cp.async.cg.shared.global [%0], [%1], 16;"
                 :: "r"(saddr), "l"(gaddr));
}
__device__ __forceinline__ void cp_commit() {
    asm volatile("cp.async.commit_group;");
}
template <int N>
__device__ __forceinline__ void cp_wait() {
    asm volatile("cp.async.wait_group %0;" :: "n"(N));
}
__device__ __forceinline__ void mma_tf32(float* d, const uint32_t* a,
                                         const uint32_t* b) {
    asm volatile(
        "mma.sync.aligned.m16n8k8.row.col.f32.tf32.tf32.f32 "
        "{%0,%1,%2,%3}, {%4,%5,%6,%7}, {%8,%9}, {%0,%1,%2,%3};"
        : "+f"(d[0]), "+f"(d[1]), "+f"(d[2]), "+f"(d[3])
        : "r"(a[0]), "r"(a[1]), "r"(a[2]), "r"(a[3]), "r"(b[0]), "r"(b[1]));
}
// split fp32 (as bits) -> tf32 hi + tf32 lo
__device__ __forceinline__ void tf32_split(uint32_t v, uint32_t& hi, uint32_t& lo) {
    float f = __uint_as_float(v);
    asm("cvt.rna.tf32.f32 %0, %1;" : "=r"(hi) : "f"(f));
    float r = f - __uint_as_float(hi);
    asm("cvt.rna.tf32.f32 %0, %1;" : "=r"(lo) : "f"(r));
}

// ----------------------------------------------------------------------------
// W transpose: W [K=512, C] row-major -> dst [C, 512] K-major
// ----------------------------------------------------------------------------
template <int MODE>
__global__ void transpose_w(const float* __restrict__ W) {
    const int C = (MODE == 0) ? CQKV : CIN;
    float* dst = (MODE == 0) ? g_WqkvT : g_WprojT;
    __shared__ float t[32][33];
    const int x  = blockIdx.x * 32 + threadIdx.x;
    const int y0 = blockIdx.y * 32;
    #pragma unroll
    for (int j = 0; j < 32; j += 8)
        t[threadIdx.y + j][threadIdx.x] = W[(size_t)(y0 + threadIdx.y + j) * C + x];
    __syncthreads();
    const int ox  = y0 + threadIdx.x;
    const int oy0 = blockIdx.x * 32;
    #pragma unroll
    for (int j = 0; j < 32; j += 8)
        dst[(size_t)(oy0 + threadIdx.y + j) * CIN + ox] = t[threadIdx.x][threadIdx.y + j];
}

// ----------------------------------------------------------------------------
// 3xtf32 GEMM: C[M,N] = A[M,512] @ B^T (B stored [N,512] K-major).
// CTA tile 128x128, 8 warps (2 M x 4 N), warp tile 64x32 (4x4 m16n8k8).
// K-chunk 16, 2-stage cp.async pipeline.
// ----------------------------------------------------------------------------
template <int MODE>
__global__ __launch_bounds__(256, 2)
void gemm_mma(const float* __restrict__ Ain, const float* __restrict__ bias,
              float* __restrict__ Out) {
    __shared__ float sA[2][128 * PITCH];
    __shared__ float sB[2][128 * PITCH];

    const float* A  = (MODE == 0) ? Ain : g_O;
    const float* Bm = (MODE == 0) ? g_WqkvT : g_WprojT;

    const int tid   = threadIdx.x;
    const int wid   = tid >> 5;
    const int lane  = tid & 31;
    const int warpM = wid >> 2;
    const int warpN = wid & 3;
    const int r4    = lane >> 2;
    const int c4    = lane & 3;
    const int M0    = blockIdx.y * 128;
    const int N0    = blockIdx.x * 128;

    const int s0row = tid >> 2,         s0seg = tid & 3;
    const int s1row = (tid + 256) >> 2, s1seg = (tid + 256) & 3;

    const float* gA0 = A  + (size_t)(M0 + s0row) * CIN + s0seg * 4;
    const float* gA1 = A  + (size_t)(M0 + s1row) * CIN + s1seg * 4;
    const float* gB0 = Bm + (size_t)(N0 + s0row) * CIN + s0seg * 4;
    const float* gB1 = Bm + (size_t)(N0 + s1row) * CIN + s1seg * 4;

    uint32_t sA0[2], sA1[2], sB0[2], sB1[2];
    #pragma unroll
    for (int b = 0; b < 2; ++b) {
        sA0[b] = smem_u32(&sA[b][s0row * PITCH + s0seg * 4]);
        sA1[b] = smem_u32(&sA[b][s1row * PITCH + s1seg * 4]);
        sB0[b] = smem_u32(&sB[b][s0row * PITCH + s0seg * 4]);
        sB1[b] = smem_u32(&sB[b][s1row * PITCH + s1seg * 4]);
    }

    float acc[4][4][4] = {};

    cp_async16(sA0[0], gA0); cp_async16(sA1[0], gA1);
    cp_async16(sB0[0], gB0); cp_async16(sB1[0], gB1);
    cp_commit();

    for (int c = 0; c < 32; ++c) {
        const int cur = c & 1;
        if (c + 1 < 32) {
            const int kt = (c + 1) * 16;
            const int nb = cur ^ 1;
            cp_async16(sA0[nb], gA0 + kt); cp_async16(sA1[nb], gA1 + kt);
            cp_async16(sB0[nb], gB0 + kt); cp_async16(sB1[nb], gB1 + kt);
            cp_commit();
            cp_wait<1>();
        } else {
            cp_wait<0>();
        }
        __syncthreads();

        const float* bufA = sA[cur];
        const float* bufB = sB[cur];
        #pragma unroll
        for (int kk = 0; kk < 2; ++kk) {
            uint32_t ahi[4][4], alo[4][4], bhi[4][2], blo[4][2];
            #pragma unroll
            for (int mt = 0; mt < 4; ++mt) {
                const uint32_t* p = (const uint32_t*)
                    &bufA[(warpM * 64 + mt * 16 + r4) * PITCH + kk * 8 + c4];
                tf32_split(p[0],             ahi[mt][0], alo[mt][0]);
                tf32_split(p[8 * PITCH],     ahi[mt][1], alo[mt][1]);
                tf32_split(p[4],             ahi[mt][2], alo[mt][2]);
                tf32_split(p[8 * PITCH + 4], ahi[mt][3], alo[mt][3]);
            }
            #pragma unroll
            for (int nt = 0; nt < 4; ++nt) {
                const uint32_t* p = (const uint32_t*)
                    &bufB[(warpN * 32 + nt * 8 + r4) * PITCH + kk * 8 + c4];
                tf32_split(p[0], bhi[nt][0], blo[nt][0]);
                tf32_split(p[4], bhi[nt][1], blo[nt][1]);
            }
            #pragma unroll
            for (int mt = 0; mt < 4; ++mt)
                #pragma unroll
                for (int nt = 0; nt < 4; ++nt) {
                    mma_tf32(acc[mt][nt], ahi[mt], bhi[nt]);
                    mma_tf32(acc[mt][nt], ahi[mt], blo[nt]);
                    mma_tf32(acc[mt][nt], alo[mt], bhi[nt]);
                }
        }
        __syncthreads();
    }

    // ---- epilogue: fragment rows r4, r4+8 / cols 2*c4, 2*c4+1 ----
    #pragma unroll
    for (int nt = 0; nt < 4; ++nt) {
        const int c0 = N0 + warpN * 32 + nt * 8 + c4 * 2;
        const float2 bv = *(const float2*)&bias[c0];
        if (MODE == 0) {
            const int h   = c0 / 96;
            const int rem = c0 - h * 96;
            const int sel = rem >> 5;
            const int d   = rem & 31;
            float* dst = (sel == 0) ? g_Q : (sel == 1) ? g_K : g_V;
            const float m = (sel == 0) ? ATT_SCALE : 1.0f;
            #pragma unroll
            for (int mt = 0; mt < 4; ++mt) {
                #pragma unroll
                for (int hh = 0; hh < 2; ++hh) {
                    const int t = M0 + warpM * 64 + mt * 16 + r4 + hh * 8;
                    const int bwin = t >> 6, n = t & 63;
                    const size_t off =
                        ((size_t)(bwin * HEADS + h) * NT + n) * HD + d;
                    float2 o;
                    o.x = (acc[mt][nt][hh * 2 + 0] + bv.x) * m;
                    o.y = (acc[mt][nt][hh * 2 + 1] + bv.y) * m;
                    *(float2*)&dst[off] = o;
                }
            }
        } else {
            #pragma unroll
            for (int mt = 0; mt < 4; ++mt) {
                #pragma unroll
                for (int hh = 0; hh < 2; ++hh) {
                    const int t = M0 + warpM * 64 + mt * 16 + r4 + hh * 8;
                    float2 o;
                    o.x = acc[mt][nt][hh * 2 + 0] + bv.x;
                    o.y = acc[mt][nt][hh * 2 + 1] + bv.y;
                    *(float2*)&Out[(size_t)t * CIN + c0] = o;
                }
            }
        }
    }
}

// ----------------------------------------------------------------------------
// Kernel 2: fused attention (proven round-1 version, unchanged)
// ----------------------------------------------------------------------------
__global__ __launch_bounds__(256)
void attn_kernel(const float* __restrict__ mask,
                 const float* __restrict__ bias_table,
                 const int*   __restrict__ rel_index)
{
    __shared__ float Qs[64][33];
    __shared__ float Kt[32][68];
    __shared__ float Vs[64][32];
    __shared__ float Ss[64][65];

    const int bid = blockIdx.x;
    const int b   = bid >> 4;
    const int h   = bid & 15;
    const int w   = b & 255;
    const int tid = threadIdx.x;

    const float* qp = g_Q + (size_t)bid * NT * HD;
    const float* kp = g_K + (size_t)bid * NT * HD;
    const float* vp = g_V + (size_t)bid * NT * HD;

    {
        const int e   = tid << 3;
        const int row = e >> 5;
        const int col = e & 31;
        float4 q0 = *(const float4*)(qp + e);
        float4 q1 = *(const float4*)(qp + e + 4);
        Qs[row][col + 0] = q0.x; Qs[row][col + 1] = q0.y;
        Qs[row][col + 2] = q0.z; Qs[row][col + 3] = q0.w;
        Qs[row][col + 4] = q1.x; Qs[row][col + 5] = q1.y;
        Qs[row][col + 6] = q1.z; Qs[row][col + 7] = q1.w;
        float4 k0 = *(const float4*)(kp + e);
        float4 k1 = *(const float4*)(kp + e + 4);
        Kt[col + 0][row] = k0.x; Kt[col + 1][row] = k0.y;
        Kt[col + 2][row] = k0.z; Kt[col + 3][row] = k0.w;
        Kt[col + 4][row] = k1.x; Kt[col + 5][row] = k1.y;
        Kt[col + 6][row] = k1.z; Kt[col + 7][row] = k1.w;
        *(float4*)&Vs[row][col]     = *(const float4*)(vp + e);
        *(float4*)&Vs[row][col + 4] = *(const float4*)(vp + e + 4);
    }
    __syncthreads();

    {
        const int i  = tid >> 2;
        const int jb = (tid & 3) << 4;
        float acc[16] = {};
        #pragma unroll
        for (int d = 0; d < 32; ++d) {
            const float qv = Qs[i][d];
            float kv[16];
            *(float4*)&kv[0]  = *(const float4*)&Kt[d][jb];
            *(float4*)&kv[4]  = *(const float4*)&Kt[d][jb + 4];
            *(float4*)&kv[8]  = *(const float4*)&Kt[d][jb + 8];
            *(float4*)&kv[12] = *(const float4*)&Kt[d][jb + 12];
            #pragma unroll
            for (int m = 0; m < 16; ++m) acc[m] = fmaf(qv, kv[m], acc[m]);
        }
        const float* mrow = mask + ((size_t)w * 64 + i) * 64;
        const int*   rrow = rel_index + i * 64;
        #pragma unroll
        for (int m = 0; m < 16; ++m) {
            const int j = jb + m;
            Ss[i][j] = acc[m] + bias_table[rrow[j] * HEADS + h] + mrow[j];
        }
    }
    __syncthreads();

    {
        const int warp = tid >> 5, lane = tid & 31;
        for (int rr = 0; rr < 8; ++rr) {
            const int r = warp * 8 + rr;
            float s0 = Ss[r][lane], s1 = Ss[r][lane + 32];
            float mx = fmaxf(s0, s1);
            #pragma unroll
            for (int o = 16; o; o >>= 1) mx = fmaxf(mx, __shfl_xor_sync(0xffffffffu, mx, o));
            float e0 = __expf(s0 - mx), e1 = __expf(s1 - mx);
            float sum = e0 + e1;
            #pragma unroll
            for (int o = 16; o; o >>= 1) sum += __shfl_xor_sync(0xffffffffu, sum, o);
            const float inv = 1.0f / sum;
            Ss[r][lane]      = e0 * inv;
            Ss[r][lane + 32] = e1 * inv;
        }
    }
    __syncthreads();

    {
        const int oi = tid >> 2;
        const int db = (tid & 3) << 3;
        float o[8] = {};
        #pragma unroll 8
        for (int j = 0; j < 64; ++j) {
            const float p = Ss[oi][j];
            float vv[8];
            *(float4*)&vv[0] = *(const float4*)&Vs[j][db];
            *(float4*)&vv[4] = *(const float4*)&Vs[j][db + 4];
            #pragma unroll
            for (int m = 0; m < 8; ++m) o[m] = fmaf(p, vv[m], o[m]);
        }
        const size_t off = ((size_t)(b * NT + oi)) * CIN + h * HD + db;
        *(float4*)&g_O[off]     = make_float4(o[0], o[1], o[2], o[3]);
        *(float4*)&g_O[off + 4] = make_float4(o[4], o[5], o[6], o[7]);
    }
}

// ----------------------------------------------------------------------------
extern "C" void kernel_launch(void* const* d_in, const int* in_sizes, int n_in,
                              void* d_out, int out_size)
{
    (void)in_sizes; (void)n_in; (void)out_size;
    const float* x          = (const float*)d_in[0];
    const float* mask       = (const float*)d_in[1];
    const float* qkv_w      = (const float*)d_in[2];
    const float* qkv_b      = (const float*)d_in[3];
    const float* proj_w     = (const float*)d_in[4];
    const float* proj_b     = (const float*)d_in[5];
    const float* bias_table = (const float*)d_in[6];
    const int*   rel_index  = (const int*)d_in[7];
    float* out = (float*)d_out;

    transpose_w<0><<<dim3(48, 16), dim3(32, 8)>>>(qkv_w);
    transpose_w<1><<<dim3(16, 16), dim3(32, 8)>>>(proj_w);
    gemm_mma<0><<<dim3(12, 512), 256>>>(x, qkv_b, nullptr);
    attn_kernel<<<BW * HEADS, 256>>>(mask, bias_table, rel_index);
    gemm_mma<1><<<dim3(4, 512), 256>>>(nullptr, proj_b, out);
}

// round 7
// speedup vs baseline: 2.1505x; 1.8326x over previous
#include <cuda_runtime.h>
#include <cstdint>
#include <cstddef>

// ============================================================================
// SwinMSA round 6:
//   GEMMs: bf16x3 error-compensated m16n8k16 mma.sync (2x fewer HMMA, 2x flops/inst)
//   Attention: mma.sync-based QK^T (tf32) + softmax + PV (3xtf32)
// ============================================================================

namespace {
constexpr int HEADS = 16;
constexpr int HD    = 32;
constexpr int NT    = 64;
constexpr int BW    = 1024;
constexpr int CIN   = 512;
constexpr int CQKV  = 1536;
constexpr float ATT_SCALE = 0.17677669529663688f;
constexpr int PITCH = 20;   // GEMM smem row pitch (floats)
}

// Scratch (__device__ globals: allocation-free rule)
__device__ float g_Q[(size_t)BW * HEADS * NT * HD];
__device__ float g_K[(size_t)BW * HEADS * NT * HD];
__device__ float g_V[(size_t)BW * HEADS * NT * HD];
__device__ float g_O[(size_t)BW * NT * CIN];
__device__ float g_WqkvT[(size_t)CQKV * CIN];
__device__ float g_WprojT[(size_t)CIN * CIN];

__device__ __forceinline__ uint32_t smem_u32(const void* p) {
    uint32_t a;
    asm("{ .reg .u64 t; cvta.to.shared.u64 t, %1; cvt.u32.u64 %0, t; }"
        : "=r"(a) : "l"(p));
    return a;
}
__device__ __forceinline__ void cp_async16(uint32_t saddr, const void* gaddr) {
    asm volatile("cp.async.cg.shared.global [%0], [%1], 16;"
                 :: "r"(saddr), "l"(gaddr));
}
__device__ __forceinline__ void cp_commit() {
    asm volatile("cp.async.commit_group;");
}
template <int N>
__device__ __forceinline__ void cp_wait() {
    asm volatile("cp.async.wait_group %0;" :: "n"(N));
}
__device__ __forceinline__ void mma_tf32(float* d, const uint32_t* a,
                                         const uint32_t* b) {
    asm volatile(
        "mma.sync.aligned.m16n8k8.row.col.f32.tf32.tf32.f32 "
        "{%0,%1,%2,%3}, {%4,%5,%6,%7}, {%8,%9}, {%0,%1,%2,%3};"
        : "+f"(d[0]), "+f"(d[1]), "+f"(d[2]), "+f"(d[3])
        : "r"(a[0]), "r"(a[1]), "r"(a[2]), "r"(a[3]), "r"(b[0]), "r"(b[1]));
}
__device__ __forceinline__ void mma_bf16(float* d, const uint32_t* a,
                                         const uint32_t* b) {
    asm volatile(
        "mma.sync.aligned.m16n8k16.row.col.f32.bf16.bf16.f32 "
        "{%0,%1,%2,%3}, {%4,%5,%6,%7}, {%8,%9}, {%0,%1,%2,%3};"
        : "+f"(d[0]), "+f"(d[1]), "+f"(d[2]), "+f"(d[3])
        : "r"(a[0]), "r"(a[1]), "r"(a[2]), "r"(a[3]), "r"(b[0]), "r"(b[1]));
}
// fp32 -> tf32 hi + lo (rna)
__device__ __forceinline__ void tf32_split(uint32_t v, uint32_t& hi, uint32_t& lo) {
    float f = __uint_as_float(v);
    asm("cvt.rna.tf32.f32 %0, %1;" : "=r"(hi) : "f"(f));
    float r = f - __uint_as_float(hi);
    asm("cvt.rna.tf32.f32 %0, %1;" : "=r"(lo) : "f"(r));
}
// float2 -> packed bf16x2 hi + bf16x2 lo   (lo half of reg = .x, hi half = .y)
__device__ __forceinline__ void bf16_split2(float2 f, uint32_t& hi, uint32_t& lo) {
    asm("cvt.rn.bf16x2.f32 %0, %1, %2;" : "=r"(hi) : "f"(f.y), "f"(f.x));
    float xh = __uint_as_float(hi << 16);
    float yh = __uint_as_float(hi & 0xffff0000u);
    float xr = f.x - xh;
    float yr = f.y - yh;
    asm("cvt.rn.bf16x2.f32 %0, %1, %2;" : "=r"(lo) : "f"(yr), "f"(xr));
}

// ----------------------------------------------------------------------------
// W transpose: W [K=512, C] row-major -> dst [C, 512] K-major
// ----------------------------------------------------------------------------
template <int MODE>
__global__ void transpose_w(const float* __restrict__ W) {
    const int C = (MODE == 0) ? CQKV : CIN;
    float* dst = (MODE == 0) ? g_WqkvT : g_WprojT;
    __shared__ float t[32][33];
    const int x  = blockIdx.x * 32 + threadIdx.x;
    const int y0 = blockIdx.y * 32;
    #pragma unroll
    for (int j = 0; j < 32; j += 8)
        t[threadIdx.y + j][threadIdx.x] = W[(size_t)(y0 + threadIdx.y + j) * C + x];
    __syncthreads();
    const int ox  = y0 + threadIdx.x;
    const int oy0 = blockIdx.x * 32;
    #pragma unroll
    for (int j = 0; j < 32; j += 8)
        dst[(size_t)(oy0 + threadIdx.y + j) * CIN + ox] = t[threadIdx.x][threadIdx.y + j];
}

// ----------------------------------------------------------------------------
// bf16x3 GEMM: C[M,N] = A[M,512] @ B^T (B stored [N,512] K-major).
// CTA 128x128, 8 warps (2M x 4N), warp tile 64x32 (4x4 m16n8k16), K-chunk 16.
// ----------------------------------------------------------------------------
template <int MODE>
__global__ __launch_bounds__(256, 2)
void gemm_mma(const float* __restrict__ Ain, const float* __restrict__ bias,
              float* __restrict__ Out) {
    __shared__ float sA[2][128 * PITCH];
    __shared__ float sB[2][128 * PITCH];

    const float* A  = (MODE == 0) ? Ain : g_O;
    const float* Bm = (MODE == 0) ? g_WqkvT : g_WprojT;

    const int tid   = threadIdx.x;
    const int wid   = tid >> 5;
    const int lane  = tid & 31;
    const int warpM = wid >> 2;
    const int warpN = wid & 3;
    const int r4    = lane >> 2;
    const int c4    = lane & 3;
    const int M0    = blockIdx.y * 128;
    const int N0    = blockIdx.x * 128;

    const int s0row = tid >> 2,         s0seg = tid & 3;
    const int s1row = (tid + 256) >> 2, s1seg = (tid + 256) & 3;

    const float* gA0 = A  + (size_t)(M0 + s0row) * CIN + s0seg * 4;
    const float* gA1 = A  + (size_t)(M0 + s1row) * CIN + s1seg * 4;
    const float* gB0 = Bm + (size_t)(N0 + s0row) * CIN + s0seg * 4;
    const float* gB1 = Bm + (size_t)(N0 + s1row) * CIN + s1seg * 4;

    uint32_t sA0[2], sA1[2], sB0[2], sB1[2];
    #pragma unroll
    for (int b = 0; b < 2; ++b) {
        sA0[b] = smem_u32(&sA[b][s0row * PITCH + s0seg * 4]);
        sA1[b] = smem_u32(&sA[b][s1row * PITCH + s1seg * 4]);
        sB0[b] = smem_u32(&sB[b][s0row * PITCH + s0seg * 4]);
        sB1[b] = smem_u32(&sB[b][s1row * PITCH + s1seg * 4]);
    }

    float acc[4][4][4] = {};

    cp_async16(sA0[0], gA0); cp_async16(sA1[0], gA1);
    cp_async16(sB0[0], gB0); cp_async16(sB1[0], gB1);
    cp_commit();

    for (int c = 0; c < 32; ++c) {
        const int cur = c & 1;
        if (c + 1 < 32) {
            const int kt = (c + 1) * 16;
            const int nb = cur ^ 1;
            cp_async16(sA0[nb], gA0 + kt); cp_async16(sA1[nb], gA1 + kt);
            cp_async16(sB0[nb], gB0 + kt); cp_async16(sB1[nb], gB1 + kt);
            cp_commit();
            cp_wait<1>();
        } else {
            cp_wait<0>();
        }
        __syncthreads();

        const float* bufA = sA[cur];
        const float* bufB = sB[cur];

        uint32_t ahi[4][4], alo[4][4], bhi[4][2], blo[4][2];
        #pragma unroll
        for (int mt = 0; mt < 4; ++mt) {
            const float* p = &bufA[(warpM * 64 + mt * 16 + r4) * PITCH + 2 * c4];
            bf16_split2(*(const float2*)(p),                 ahi[mt][0], alo[mt][0]);
            bf16_split2(*(const float2*)(p + 8 * PITCH),     ahi[mt][1], alo[mt][1]);
            bf16_split2(*(const float2*)(p + 8),             ahi[mt][2], alo[mt][2]);
            bf16_split2(*(const float2*)(p + 8 * PITCH + 8), ahi[mt][3], alo[mt][3]);
        }
        #pragma unroll
        for (int nt = 0; nt < 4; ++nt) {
            const float* p = &bufB[(warpN * 32 + nt * 8 + r4) * PITCH + 2 * c4];
            bf16_split2(*(const float2*)(p),     bhi[nt][0], blo[nt][0]);
            bf16_split2(*(const float2*)(p + 8), bhi[nt][1], blo[nt][1]);
        }
        #pragma unroll
        for (int mt = 0; mt < 4; ++mt)
            #pragma unroll
            for (int nt = 0; nt < 4; ++nt) {
                mma_bf16(acc[mt][nt], ahi[mt], bhi[nt]);
                mma_bf16(acc[mt][nt], ahi[mt], blo[nt]);
                mma_bf16(acc[mt][nt], alo[mt], bhi[nt]);
            }
        __syncthreads();
    }

    // ---- epilogue: fragment rows r4, r4+8 / cols 2*c4, 2*c4+1 ----
    #pragma unroll
    for (int nt = 0; nt < 4; ++nt) {
        const int c0 = N0 + warpN * 32 + nt * 8 + c4 * 2;
        const float2 bv = *(const float2*)&bias[c0];
        if (MODE == 0) {
            const int h   = c0 / 96;
            const int rem = c0 - h * 96;
            const int sel = rem >> 5;
            const int d   = rem & 31;
            float* dst = (sel == 0) ? g_Q : (sel == 1) ? g_K : g_V;
            const float m = (sel == 0) ? ATT_SCALE : 1.0f;
            #pragma unroll
            for (int mt = 0; mt < 4; ++mt) {
                #pragma unroll
                for (int hh = 0; hh < 2; ++hh) {
                    const int t = M0 + warpM * 64 + mt * 16 + r4 + hh * 8;
                    const int bwin = t >> 6, n = t & 63;
                    const size_t off =
                        ((size_t)(bwin * HEADS + h) * NT + n) * HD + d;
                    float2 o;
                    o.x = (acc[mt][nt][hh * 2 + 0] + bv.x) * m;
                    o.y = (acc[mt][nt][hh * 2 + 1] + bv.y) * m;
                    *(float2*)&dst[off] = o;
                }
            }
        } else {
            #pragma unroll
            for (int mt = 0; mt < 4; ++mt) {
                #pragma unroll
                for (int hh = 0; hh < 2; ++hh) {
                    const int t = M0 + warpM * 64 + mt * 16 + r4 + hh * 8;
                    float2 o;
                    o.x = acc[mt][nt][hh * 2 + 0] + bv.x;
                    o.y = acc[mt][nt][hh * 2 + 1] + bv.y;
                    *(float2*)&Out[(size_t)t * CIN + c0] = o;
                }
            }
        }
    }
}

// ----------------------------------------------------------------------------
// Attention, mma-based. One block (256 thr, 8 warps) per (window b, head h).
// QK^T: tf32 mma (raw fp32 bits, truncation — error ~1e-4 abs, harmless).
// softmax: warp-shuffle (unchanged math).
// PV: 3xtf32 mma (compensated).
// ----------------------------------------------------------------------------
__global__ __launch_bounds__(256)
void attn_kernel(const float* __restrict__ mask,
                 const float* __restrict__ bias_table,
                 const int*   __restrict__ rel_index)
{
    __shared__ float Qs[64 * 36];
    __shared__ float Ks[64 * 36];
    __shared__ float Vt[32 * 68];   // V transposed: Vt[d][j]
    __shared__ float Ss[64 * 68];

    const int bid = blockIdx.x;
    const int b   = bid >> 4;
    const int h   = bid & 15;
    const int w   = b & 255;
    const int tid = threadIdx.x;
    const int wid = tid >> 5, lane = tid & 31;
    const int r4  = lane >> 2, c4 = lane & 3;

    const float* qp = g_Q + (size_t)bid * (NT * HD);
    const float* kp = g_K + (size_t)bid * (NT * HD);
    const float* vp = g_V + (size_t)bid * (NT * HD);

    // ---- load tiles ----
    {
        const int row = tid >> 2, cs = (tid & 3) << 3;
        float4 q0 = *(const float4*)(qp + row * 32 + cs);
        float4 q1 = *(const float4*)(qp + row * 32 + cs + 4);
        *(float4*)&Qs[row * 36 + cs]     = q0;
        *(float4*)&Qs[row * 36 + cs + 4] = q1;
        float4 k0 = *(const float4*)(kp + row * 32 + cs);
        float4 k1 = *(const float4*)(kp + row * 32 + cs + 4);
        *(float4*)&Ks[row * 36 + cs]     = k0;
        *(float4*)&Ks[row * 36 + cs + 4] = k1;
        float4 v0 = *(const float4*)(vp + row * 32 + cs);
        float4 v1 = *(const float4*)(vp + row * 32 + cs + 4);
        Vt[(cs + 0) * 68 + row] = v0.x; Vt[(cs + 1) * 68 + row] = v0.y;
        Vt[(cs + 2) * 68 + row] = v0.z; Vt[(cs + 3) * 68 + row] = v0.w;
        Vt[(cs + 4) * 68 + row] = v1.x; Vt[(cs + 5) * 68 + row] = v1.y;
        Vt[(cs + 6) * 68 + row] = v1.z; Vt[(cs + 7) * 68 + row] = v1.w;
    }
    __syncthreads();

    // ---- S = Q K^T (+bias +mask) : warp grid 4M x 2N, warp tile 16x32 ----
    {
        const int rm = (wid >> 1) * 16;
        const int cn = (wid & 1) * 32;
        float acc[4][4] = {};
        #pragma unroll
        for (int kk = 0; kk < 4; ++kk) {
            uint32_t a[4];
            const uint32_t* pa = (const uint32_t*)&Qs[(rm + r4) * 36 + kk * 8 + c4];
            a[0] = pa[0];
            a[1] = pa[8 * 36];
            a[2] = pa[4];
            a[3] = pa[8 * 36 + 4];
            #pragma unroll
            for (int nt = 0; nt < 4; ++nt) {
                uint32_t bf[2];
                const uint32_t* pb =
                    (const uint32_t*)&Ks[(cn + nt * 8 + r4) * 36 + kk * 8 + c4];
                bf[0] = pb[0];
                bf[1] = pb[4];
                mma_tf32(acc[nt], a, bf);
            }
        }
        const int i0 = rm + r4, i1 = i0 + 8;
        #pragma unroll
        for (int nt = 0; nt < 4; ++nt) {
            const int jc = cn + nt * 8 + 2 * c4;
            const int2 rI0 = *(const int2*)&rel_index[i0 * 64 + jc];
            const int2 rI1 = *(const int2*)&rel_index[i1 * 64 + jc];
            const float2 m0 = *(const float2*)&mask[((size_t)w * 64 + i0) * 64 + jc];
            const float2 m1 = *(const float2*)&mask[((size_t)w * 64 + i1) * 64 + jc];
            float2 s0, s1;
            s0.x = acc[nt][0] + bias_table[rI0.x * HEADS + h] + m0.x;
            s0.y = acc[nt][1] + bias_table[rI0.y * HEADS + h] + m0.y;
            s1.x = acc[nt][2] + bias_table[rI1.x * HEADS + h] + m1.x;
            s1.y = acc[nt][3] + bias_table[rI1.y * HEADS + h] + m1.y;
            *(float2*)&Ss[i0 * 68 + jc] = s0;
            *(float2*)&Ss[i1 * 68 + jc] = s1;
        }
    }
    __syncthreads();

    // ---- row softmax: warp handles 8 rows ----
    {
        #pragma unroll
        for (int rr = 0; rr < 8; ++rr) {
            const int r = wid * 8 + rr;
            float s0 = Ss[r * 68 + lane], s1 = Ss[r * 68 + lane + 32];
            float mx = fmaxf(s0, s1);
            #pragma unroll
            for (int o = 16; o; o >>= 1) mx = fmaxf(mx, __shfl_xor_sync(0xffffffffu, mx, o));
            float e0 = __expf(s0 - mx), e1 = __expf(s1 - mx);
            float sum = e0 + e1;
            #pragma unroll
            for (int o = 16; o; o >>= 1) sum += __shfl_xor_sync(0xffffffffu, sum, o);
            const float inv = 1.0f / sum;
            Ss[r * 68 + lane]      = e0 * inv;
            Ss[r * 68 + lane + 32] = e1 * inv;
        }
    }
    __syncthreads();

    // ---- O = P V : warp grid 4M x 2N, warp tile 16x16, 3xtf32 ----
    {
        const int rm = (wid >> 1) * 16;
        const int cn = (wid & 1) * 16;
        float acc[2][4] = {};
        #pragma unroll
        for (int ks = 0; ks < 8; ++ks) {
            uint32_t ahi[4], alo[4];
            const uint32_t* pa = (const uint32_t*)&Ss[(rm + r4) * 68 + ks * 8 + c4];
            tf32_split(pa[0],          ahi[0], alo[0]);
            tf32_split(pa[8 * 68],     ahi[1], alo[1]);
            tf32_split(pa[4],          ahi[2], alo[2]);
            tf32_split(pa[8 * 68 + 4], ahi[3], alo[3]);
            #pragma unroll
            for (int nt = 0; nt < 2; ++nt) {
                const uint32_t* pb =
                    (const uint32_t*)&Vt[(cn + nt * 8 + r4) * 68 + ks * 8 + c4];
                uint32_t bh[2], bl[2];
                tf32_split(pb[0], bh[0], bl[0]);
                tf32_split(pb[4], bh[1], bl[1]);
                mma_tf32(acc[nt], ahi, bh);
                mma_tf32(acc[nt], ahi, bl);
                mma_tf32(acc[nt], alo, bh);
            }
        }
        const int i0 = rm + r4;
        #pragma unroll
        for (int nt = 0; nt < 2; ++nt) {
            const int d0 = cn + nt * 8 + 2 * c4;
            const size_t off = ((size_t)b * NT + i0) * CIN + h * HD + d0;
            *(float2*)&g_O[off]             = make_float2(acc[nt][0], acc[nt][1]);
            *(float2*)&g_O[off + 8 * CIN]   = make_float2(acc[nt][2], acc[nt][3]);
        }
    }
}

// ----------------------------------------------------------------------------
extern "C" void kernel_launch(void* const* d_in, const int* in_sizes, int n_in,
                              void* d_out, int out_size)
{
    (void)in_sizes; (void)n_in; (void)out_size;
    const float* x          = (const float*)d_in[0];
    const float* mask       = (const float*)d_in[1];
    const float* qkv_w      = (const float*)d_in[2];
    const float* qkv_b      = (const float*)d_in[3];
    const float* proj_w     = (const float*)d_in[4];
    const float* proj_b     = (const float*)d_in[5];
    const float* bias_table = (const float*)d_in[6];
    const int*   rel_index  = (const int*)d_in[7];
    float* out = (float*)d_out;

    transpose_w<0><<<dim3(48, 16), dim3(32, 8)>>>(qkv_w);
    transpose_w<1><<<dim3(16, 16), dim3(32, 8)>>>(proj_w);
    gemm_mma<0><<<dim3(12, 512), 256>>>(x, qkv_b, nullptr);
    attn_kernel<<<BW * HEADS, 256>>>(mask, bias_table, rel_index);
    gemm_mma<1><<<dim3(4, 512), 256>>>(nullptr, proj_b, out);
}

// round 8
// speedup vs baseline: 2.1845x; 1.0158x over previous
#include <cuda_runtime.h>
#include <cstdint>
#include <cstddef>

// ============================================================================
// SwinMSA round 7: hoist bf16 hi/lo splitting out of all inner loops.
//   prep: x, WqkvT, WprojT pre-split into packed bf16x2 hi/lo (uint32/kpair)
//   gemm: pure LDS+HMMA bf16x3 (XOR-swizzled 32B rows, no padding)
//   attn: QK tf32 -> softmax packs P into bf16 hi/lo -> PV pure bf16x3
//         -> O written pre-split (feeds proj gemm directly)
// ============================================================================

namespace {
constexpr int HEADS = 16;
constexpr int HD    = 32;
constexpr int NT    = 64;
constexpr int BW    = 1024;
constexpr int CIN   = 512;
constexpr int CQKV  = 1536;
constexpr int KP    = CIN / 2;      // 256 kpairs per row
constexpr float ATT_SCALE = 0.17677669529663688f;
}

// -------- __device__ scratch (allocation-free rule) --------
__device__ float    g_Q[(size_t)BW * HEADS * NT * HD];
__device__ float    g_K[(size_t)BW * HEADS * NT * HD];
__device__ float    g_V[(size_t)BW * HEADS * NT * HD];
__device__ float    g_WqkvT[(size_t)CQKV * CIN];
__device__ float    g_WprojT[(size_t)CIN * CIN];
__device__ uint32_t g_Xhi[(size_t)BW * NT * KP],  g_Xlo[(size_t)BW * NT * KP];
__device__ uint32_t g_Ohi[(size_t)BW * NT * KP],  g_Olo[(size_t)BW * NT * KP];
__device__ uint32_t g_Wh0[(size_t)CQKV * KP],     g_Wl0[(size_t)CQKV * KP];
__device__ uint32_t g_Wh1[(size_t)CIN * KP],      g_Wl1[(size_t)CIN * KP];

__device__ __forceinline__ uint32_t smem_u32(const void* p) {
    uint32_t a;
    asm("{ .reg .u64 t; cvta.to.shared.u64 t, %1; cvt.u32.u64 %0, t; }"
        : "=r"(a) : "l"(p));
    return a;
}
__device__ __forceinline__ void cp_async16(uint32_t saddr, const void* gaddr) {
    asm volatile("cp.async.cg.shared.global [%0], [%1], 16;"
                 :: "r"(saddr), "l"(gaddr));
}
__device__ __forceinline__ void cp_commit() {
    asm volatile("cp.async.commit_group;");
}
template <int N>
__device__ __forceinline__ void cp_wait() {
    asm volatile("cp.async.wait_group %0;" :: "n"(N));
}
__device__ __forceinline__ void mma_tf32(float* d, const uint32_t* a,
                                         const uint32_t* b) {
    asm volatile(
        "mma.sync.aligned.m16n8k8.row.col.f32.tf32.tf32.f32 "
        "{%0,%1,%2,%3}, {%4,%5,%6,%7}, {%8,%9}, {%0,%1,%2,%3};"
        : "+f"(d[0]), "+f"(d[1]), "+f"(d[2]), "+f"(d[3])
        : "r"(a[0]), "r"(a[1]), "r"(a[2]), "r"(a[3]), "r"(b[0]), "r"(b[1]));
}
__device__ __forceinline__ void mma_bf16(float* d, const uint32_t* a,
                                         const uint32_t* b) {
    asm volatile(
        "mma.sync.aligned.m16n8k16.row.col.f32.bf16.bf16.f32 "
        "{%0,%1,%2,%3}, {%4,%5,%6,%7}, {%8,%9}, {%0,%1,%2,%3};"
        : "+f"(d[0]), "+f"(d[1]), "+f"(d[2]), "+f"(d[3])
        : "r"(a[0]), "r"(a[1]), "r"(a[2]), "r"(a[3]), "r"(b[0]), "r"(b[1]));
}
// float2 -> packed bf16x2 hi + lo  (lower half = .x)
__device__ __forceinline__ void bf16_split2(float2 f, uint32_t& hi, uint32_t& lo) {
    asm("cvt.rn.bf16x2.f32 %0, %1, %2;" : "=r"(hi) : "f"(f.y), "f"(f.x));
    float xr = f.x - __uint_as_float(hi << 16);
    float yr = f.y - __uint_as_float(hi & 0xffff0000u);
    asm("cvt.rn.bf16x2.f32 %0, %1, %2;" : "=r"(lo) : "f"(yr), "f"(xr));
}

// ----------------------------------------------------------------------------
// W transpose: W [K=512, C] row-major -> dst [C, 512] K-major
// ----------------------------------------------------------------------------
template <int MODE>
__global__ void transpose_w(const float* __restrict__ W) {
    const int C = (MODE == 0) ? CQKV : CIN;
    float* dst = (MODE == 0) ? g_WqkvT : g_WprojT;
    __shared__ float t[32][33];
    const int x  = blockIdx.x * 32 + threadIdx.x;
    const int y0 = blockIdx.y * 32;
    #pragma unroll
    for (int j = 0; j < 32; j += 8)
        t[threadIdx.y + j][threadIdx.x] = W[(size_t)(y0 + threadIdx.y + j) * C + x];
    __syncthreads();
    const int ox  = y0 + threadIdx.x;
    const int oy0 = blockIdx.x * 32;
    #pragma unroll
    for (int j = 0; j < 32; j += 8)
        dst[(size_t)(oy0 + threadIdx.y + j) * CIN + ox] = t[threadIdx.x][threadIdx.y + j];
}

// ----------------------------------------------------------------------------
// Split fp32 stream into packed bf16x2 hi/lo (2 kpairs per float4)
// ----------------------------------------------------------------------------
__global__ void split_kernel(const float* __restrict__ src,
                             uint32_t* __restrict__ hi,
                             uint32_t* __restrict__ lo, int n4) {
    const int i = blockIdx.x * blockDim.x + threadIdx.x;
    if (i >= n4) return;
    float4 v = ((const float4*)src)[i];
    uint32_t h0, l0, h1, l1;
    bf16_split2(make_float2(v.x, v.y), h0, l0);
    bf16_split2(make_float2(v.z, v.w), h1, l1);
    ((uint2*)hi)[i] = make_uint2(h0, h1);
    ((uint2*)lo)[i] = make_uint2(l0, l1);
}

// ----------------------------------------------------------------------------
// bf16x3 GEMM on pre-split operands. C[M,N] = A @ B^T.
// CTA 128x128, 8 warps (2M x 4N), warp tile 64x32 (4x4 m16n8k16), K-chunk 16.
// smem rows: 8 uint32 (kpairs), 16B-block XOR swizzle (half ^ ((row>>2)&1)).
// ----------------------------------------------------------------------------
template <int MODE>
__global__ __launch_bounds__(256, 2)
void gemm_mma(const float* __restrict__ bias, float* __restrict__ Out) {
    __shared__ uint32_t sAh[2][1024], sAl[2][1024], sBh[2][1024], sBl[2][1024];

    const uint32_t* Ahi = MODE ? g_Ohi : g_Xhi;
    const uint32_t* Alo = MODE ? g_Olo : g_Xlo;
    const uint32_t* Bhi = MODE ? g_Wh1 : g_Wh0;
    const uint32_t* Blo = MODE ? g_Wl1 : g_Wl0;

    const int tid   = threadIdx.x;
    const int wid   = tid >> 5;
    const int lane  = tid & 31;
    const int warpM = wid >> 2;
    const int warpN = wid & 3;
    const int r4    = lane >> 2;
    const int c4    = lane & 3;
    const int M0    = blockIdx.y * 128;
    const int N0    = blockIdx.x * 128;

    // cp.async slot: row = tid>>1 (0..127), half = tid&1
    const int crow = tid >> 1, chalf = tid & 1;
    const uint32_t soff = (uint32_t)(crow * 8 + ((chalf ^ ((crow >> 2) & 1)) << 2)) * 4u;
    const size_t gAo = (size_t)(M0 + crow) * KP + chalf * 4;
    const size_t gBo = (size_t)(N0 + crow) * KP + chalf * 4;

    uint32_t dAh[2], dAl[2], dBh[2], dBl[2];
    #pragma unroll
    for (int b = 0; b < 2; ++b) {
        dAh[b] = smem_u32(sAh[b]) + soff;
        dAl[b] = smem_u32(sAl[b]) + soff;
        dBh[b] = smem_u32(sBh[b]) + soff;
        dBl[b] = smem_u32(sBl[b]) + soff;
    }

    float acc[4][4][4] = {};

    cp_async16(dAh[0], Ahi + gAo); cp_async16(dAl[0], Alo + gAo);
    cp_async16(dBh[0], Bhi + gBo); cp_async16(dBl[0], Blo + gBo);
    cp_commit();

    // fragment smem indices (row*8 + swz-half*4 + c4)
    const int axr[4] = { ((warpM * 64 +  0 + 0) >> 2) & 1, 0, 0, 0 }; (void)axr;

    for (int c = 0; c < 32; ++c) {
        const int cur = c & 1;
        if (c + 1 < 32) {
            const int kt = (c + 1) * 8;
            const int nb = cur ^ 1;
            cp_async16(dAh[nb], Ahi + gAo + kt); cp_async16(dAl[nb], Alo + gAo + kt);
            cp_async16(dBh[nb], Bhi + gBo + kt); cp_async16(dBl[nb], Blo + gBo + kt);
            cp_commit();
            cp_wait<1>();
        } else {
            cp_wait<0>();
        }
        __syncthreads();

        uint32_t ah[4][4], al[4][4], bh[4][2], bl[4][2];
        #pragma unroll
        for (int mt = 0; mt < 4; ++mt) {
            const int r0 = warpM * 64 + mt * 16 + r4;
            const int r1 = r0 + 8;
            const int x0 = (r0 >> 2) & 1, x1 = (r1 >> 2) & 1;
            const int i00 = r0 * 8 + (x0 << 2) + c4;        // half 0 ^ swz
            const int i01 = r0 * 8 + ((1 ^ x0) << 2) + c4;  // half 1 ^ swz
            const int i10 = r1 * 8 + (x1 << 2) + c4;
            const int i11 = r1 * 8 + ((1 ^ x1) << 2) + c4;
            ah[mt][0] = sAh[cur][i00]; ah[mt][1] = sAh[cur][i10];
            ah[mt][2] = sAh[cur][i01]; ah[mt][3] = sAh[cur][i11];
            al[mt][0] = sAl[cur][i00]; al[mt][1] = sAl[cur][i10];
            al[mt][2] = sAl[cur][i01]; al[mt][3] = sAl[cur][i11];
        }
        #pragma unroll
        for (int nt = 0; nt < 4; ++nt) {
            const int r0 = warpN * 32 + nt * 8 + r4;
            const int x0 = (r0 >> 2) & 1;
            const int i00 = r0 * 8 + (x0 << 2) + c4;
            const int i01 = r0 * 8 + ((1 ^ x0) << 2) + c4;
            bh[nt][0] = sBh[cur][i00]; bh[nt][1] = sBh[cur][i01];
            bl[nt][0] = sBl[cur][i00]; bl[nt][1] = sBl[cur][i01];
        }
        #pragma unroll
        for (int mt = 0; mt < 4; ++mt)
            #pragma unroll
            for (int nt = 0; nt < 4; ++nt) {
                mma_bf16(acc[mt][nt], ah[mt], bh[nt]);
                mma_bf16(acc[mt][nt], ah[mt], bl[nt]);
                mma_bf16(acc[mt][nt], al[mt], bh[nt]);
            }
        __syncthreads();
    }

    // ---- epilogue ----
    #pragma unroll
    for (int nt = 0; nt < 4; ++nt) {
        const int c0 = N0 + warpN * 32 + nt * 8 + c4 * 2;
        const float2 bv = *(const float2*)&bias[c0];
        if (MODE == 0) {
            const int h   = c0 / 96;
            const int rem = c0 - h * 96;
            const int sel = rem >> 5;
            const int d   = rem & 31;
            float* dst = (sel == 0) ? g_Q : (sel == 1) ? g_K : g_V;
            const float m = (sel == 0) ? ATT_SCALE : 1.0f;
            #pragma unroll
            for (int mt = 0; mt < 4; ++mt)
                #pragma unroll
                for (int hh = 0; hh < 2; ++hh) {
                    const int t = M0 + warpM * 64 + mt * 16 + r4 + hh * 8;
                    const int bwin = t >> 6, n = t & 63;
                    const size_t off =
                        ((size_t)(bwin * HEADS + h) * NT + n) * HD + d;
                    float2 o;
                    o.x = (acc[mt][nt][hh * 2 + 0] + bv.x) * m;
                    o.y = (acc[mt][nt][hh * 2 + 1] + bv.y) * m;
                    *(float2*)&dst[off] = o;
                }
        } else {
            #pragma unroll
            for (int mt = 0; mt < 4; ++mt)
                #pragma unroll
                for (int hh = 0; hh < 2; ++hh) {
                    const int t = M0 + warpM * 64 + mt * 16 + r4 + hh * 8;
                    float2 o;
                    o.x = acc[mt][nt][hh * 2 + 0] + bv.x;
                    o.y = acc[mt][nt][hh * 2 + 1] + bv.y;
                    *(float2*)&Out[(size_t)t * CIN + c0] = o;
                }
        }
    }
}

// ----------------------------------------------------------------------------
// Attention. QK^T tf32 -> softmax (packs P into bf16 hi/lo) -> PV bf16x3.
// Writes O pre-split (g_Ohi/g_Olo) for the proj GEMM.
// ----------------------------------------------------------------------------
__global__ __launch_bounds__(256)
void attn_kernel(const float* __restrict__ mask,
                 const float* __restrict__ bias_table,
                 const int*   __restrict__ rel_index)
{
    __shared__ float    Qs[64 * 36];      // reused as PhHi after QK
    __shared__ float    Ks[64 * 36];      // reused as PhLo after QK
    __shared__ float    Ss[64 * 68];
    __shared__ uint32_t VtHi[32 * 36];
    __shared__ uint32_t VtLo[32 * 36];
    uint32_t* PhHi = (uint32_t*)Qs;       // [64][36] row=i, col=jpair
    uint32_t* PhLo = (uint32_t*)Ks;

    const int bid = blockIdx.x;
    const int b   = bid >> 4;
    const int h   = bid & 15;
    const int w   = b & 255;
    const int tid = threadIdx.x;
    const int wid = tid >> 5, lane = tid & 31;
    const int r4  = lane >> 2, c4 = lane & 3;

    const float* qp = g_Q + (size_t)bid * (NT * HD);
    const float* kp = g_K + (size_t)bid * (NT * HD);
    const float* vp = g_V + (size_t)bid * (NT * HD);

    // ---- load Q,K tiles; V -> transposed split bf16 tiles ----
    {
        const int row = tid >> 2, cs = (tid & 3) << 3;
        *(float4*)&Qs[row * 36 + cs]     = *(const float4*)(qp + row * 32 + cs);
        *(float4*)&Qs[row * 36 + cs + 4] = *(const float4*)(qp + row * 32 + cs + 4);
        *(float4*)&Ks[row * 36 + cs]     = *(const float4*)(kp + row * 32 + cs);
        *(float4*)&Ks[row * 36 + cs + 4] = *(const float4*)(kp + row * 32 + cs + 4);
        // V: thread handles jpair jp = tid>>3 (0..31), d block = (tid&7)*4
        const int jp = tid >> 3, d0 = (tid & 7) << 2;
        float4 v0 = *(const float4*)(vp + (2 * jp)     * 32 + d0);
        float4 v1 = *(const float4*)(vp + (2 * jp + 1) * 32 + d0);
        uint32_t hh, ll;
        bf16_split2(make_float2(v0.x, v1.x), hh, ll);
        VtHi[(d0 + 0) * 36 + jp] = hh; VtLo[(d0 + 0) * 36 + jp] = ll;
        bf16_split2(make_float2(v0.y, v1.y), hh, ll);
        VtHi[(d0 + 1) * 36 + jp] = hh; VtLo[(d0 + 1) * 36 + jp] = ll;
        bf16_split2(make_float2(v0.z, v1.z), hh, ll);
        VtHi[(d0 + 2) * 36 + jp] = hh; VtLo[(d0 + 2) * 36 + jp] = ll;
        bf16_split2(make_float2(v0.w, v1.w), hh, ll);
        VtHi[(d0 + 3) * 36 + jp] = hh; VtLo[(d0 + 3) * 36 + jp] = ll;
    }
    __syncthreads();

    // ---- S = Q K^T (+bias +mask): warp grid 4M x 2N, warp tile 16x32, tf32 ----
    {
        const int rm = (wid >> 1) * 16;
        const int cn = (wid & 1) * 32;
        float acc[4][4] = {};
        #pragma unroll
        for (int kk = 0; kk < 4; ++kk) {
            uint32_t a[4];
            const uint32_t* pa = (const uint32_t*)&Qs[(rm + r4) * 36 + kk * 8 + c4];
            a[0] = pa[0]; a[1] = pa[8 * 36]; a[2] = pa[4]; a[3] = pa[8 * 36 + 4];
            #pragma unroll
            for (int nt = 0; nt < 4; ++nt) {
                const uint32_t* pb =
                    (const uint32_t*)&Ks[(cn + nt * 8 + r4) * 36 + kk * 8 + c4];
                uint32_t bf[2] = { pb[0], pb[4] };
                mma_tf32(acc[nt], a, bf);
            }
        }
        const int i0 = rm + r4, i1 = i0 + 8;
        #pragma unroll
        for (int nt = 0; nt < 4; ++nt) {
            const int jc = cn + nt * 8 + 2 * c4;
            const int2 rI0 = *(const int2*)&rel_index[i0 * 64 + jc];
            const int2 rI1 = *(const int2*)&rel_index[i1 * 64 + jc];
            const float2 m0 = *(const float2*)&mask[((size_t)w * 64 + i0) * 64 + jc];
            const float2 m1 = *(const float2*)&mask[((size_t)w * 64 + i1) * 64 + jc];
            float2 s0, s1;
            s0.x = acc[nt][0] + bias_table[rI0.x * HEADS + h] + m0.x;
            s0.y = acc[nt][1] + bias_table[rI0.y * HEADS + h] + m0.y;
            s1.x = acc[nt][2] + bias_table[rI1.x * HEADS + h] + m1.x;
            s1.y = acc[nt][3] + bias_table[rI1.y * HEADS + h] + m1.y;
            *(float2*)&Ss[i0 * 68 + jc] = s0;
            *(float2*)&Ss[i1 * 68 + jc] = s1;
        }
    }
    __syncthreads();

    // ---- softmax: lane owns columns 2*lane, 2*lane+1; pack P to bf16 hi/lo ----
    {
        #pragma unroll
        for (int rr = 0; rr < 8; ++rr) {
            const int r = wid * 8 + rr;
            float2 s = *(const float2*)&Ss[r * 68 + 2 * lane];
            float mx = fmaxf(s.x, s.y);
            #pragma unroll
            for (int o = 16; o; o >>= 1) mx = fmaxf(mx, __shfl_xor_sync(0xffffffffu, mx, o));
            float e0 = __expf(s.x - mx), e1 = __expf(s.y - mx);
            float sum = e0 + e1;
            #pragma unroll
            for (int o = 16; o; o >>= 1) sum += __shfl_xor_sync(0xffffffffu, sum, o);
            const float inv = 1.0f / sum;
            uint32_t hh, ll;
            bf16_split2(make_float2(e0 * inv, e1 * inv), hh, ll);
            PhHi[r * 36 + lane] = hh;
            PhLo[r * 36 + lane] = ll;
        }
    }
    __syncthreads();

    // ---- O = P V : warp grid 4M x 2N, warp tile 16x16, bf16x3 ----
    {
        const int rm = (wid >> 1) * 16;
        const int cn = (wid & 1) * 16;
        float acc[2][4] = {};
        #pragma unroll
        for (int ks = 0; ks < 4; ++ks) {      // K=64 -> 4 chunks of 16
            uint32_t ah[4], al[4];
            const uint32_t* ph = &PhHi[(rm + r4) * 36 + ks * 8 + c4];
            const uint32_t* pl = &PhLo[(rm + r4) * 36 + ks * 8 + c4];
            ah[0] = ph[0]; ah[1] = ph[8 * 36]; ah[2] = ph[4]; ah[3] = ph[8 * 36 + 4];
            al[0] = pl[0]; al[1] = pl[8 * 36]; al[2] = pl[4]; al[3] = pl[8 * 36 + 4];
            #pragma unroll
            for (int nt = 0; nt < 2; ++nt) {
                const int vr = (cn + nt * 8 + r4) * 36 + ks * 8 + c4;
                uint32_t bh[2] = { VtHi[vr], VtHi[vr + 4] };
                uint32_t bl[2] = { VtLo[vr], VtLo[vr + 4] };
                mma_bf16(acc[nt], ah, bh);
                mma_bf16(acc[nt], ah, bl);
                mma_bf16(acc[nt], al, bh);
            }
        }
        // write O pre-split: rows rm+r4, rm+r4+8; cols d0, d0+1 (adjacent)
        const int i0 = rm + r4;
        #pragma unroll
        for (int nt = 0; nt < 2; ++nt) {
            const int d0 = cn + nt * 8 + 2 * c4;
            const int kpair = h * 16 + (d0 >> 1);
            uint32_t hh, ll;
            bf16_split2(make_float2(acc[nt][0], acc[nt][1]), hh, ll);
            g_Ohi[((size_t)b * NT + i0) * KP + kpair] = hh;
            g_Olo[((size_t)b * NT + i0) * KP + kpair] = ll;
            bf16_split2(make_float2(acc[nt][2], acc[nt][3]), hh, ll);
            g_Ohi[((size_t)b * NT + i0 + 8) * KP + kpair] = hh;
            g_Olo[((size_t)b * NT + i0 + 8) * KP + kpair] = ll;
        }
    }
}

// ----------------------------------------------------------------------------
extern "C" void kernel_launch(void* const* d_in, const int* in_sizes, int n_in,
                              void* d_out, int out_size)
{
    (void)in_sizes; (void)n_in; (void)out_size;
    const float* x          = (const float*)d_in[0];
    const float* mask       = (const float*)d_in[1];
    const float* qkv_w      = (const float*)d_in[2];
    const float* qkv_b      = (const float*)d_in[3];
    const float* proj_w     = (const float*)d_in[4];
    const float* proj_b     = (const float*)d_in[5];
    const float* bias_table = (const float*)d_in[6];
    const int*   rel_index  = (const int*)d_in[7];
    float* out = (float*)d_out;

    uint32_t *xhi, *xlo, *wh0, *wl0, *wh1, *wl1;
    float *wqkvT, *wprojT;
    cudaGetSymbolAddress((void**)&xhi, g_Xhi);
    cudaGetSymbolAddress((void**)&xlo, g_Xlo);
    cudaGetSymbolAddress((void**)&wh0, g_Wh0);
    cudaGetSymbolAddress((void**)&wl0, g_Wl0);
    cudaGetSymbolAddress((void**)&wh1, g_Wh1);
    cudaGetSymbolAddress((void**)&wl1, g_Wl1);
    cudaGetSymbolAddress((void**)&wqkvT, g_WqkvT);
    cudaGetSymbolAddress((void**)&wprojT, g_WprojT);

    transpose_w<0><<<dim3(48, 16), dim3(32, 8)>>>(qkv_w);
    transpose_w<1><<<dim3(16, 16), dim3(32, 8)>>>(proj_w);
    split_kernel<<<32768, 256>>>(x, xhi, xlo, BW * NT * CIN / 4);
    split_kernel<<<768, 256>>>(wqkvT, wh0, wl0, CQKV * CIN / 4);
    split_kernel<<<256, 256>>>(wprojT, wh1, wl1, CIN * CIN / 4);
    gemm_mma<0><<<dim3(12, 512), 256>>>(qkv_b, nullptr);
    attn_kernel<<<BW * HEADS, 256>>>(mask, bias_table, rel_index);
    gemm_mma<1><<<dim3(4, 512), 256>>>(proj_b, out);
}